// round 16
// baseline (speedup 1.0000x reference)
#include <cuda_runtime.h>
#include <cuda_fp16.h>
#include <math.h>
#include <stdint.h>

#define H_DIM 128
#define ED_DIM 16
#define ETILE 128
#define THREADS 256
#define MAX_N 20000
#define MAX_E 640000
#define LDH 136            // half pitch; 272B rows -> ldmatrix conflict-free

// ---------------- device scratch ----------------
__device__ __align__(16) float g_msg[MAX_N * H_DIM];
__device__ __align__(16) float g_coord[MAX_N * 3];
__device__ __align__(16) __half g_h16[MAX_N * H_DIM];
__device__ __align__(16) __half g_ea16[MAX_E * ED_DIM];
// 8 chunks [128][LDH]: 0,1=We1 k0..255, 2=We1 tail(ea rows 0..15, dist row 16),
// 3=We2, 4=Wx1, 5,6=Wh1, 7=Wh2
__device__ __align__(16) __half g_B[8 * 128 * LDH];

// silu via tanh.approx.f32 (R8-proven)
__device__ __forceinline__ float silu_t(float v) {
    float t;
    asm("tanh.approx.f32 %0, %1;" : "=f"(t) : "f"(v * 0.5f));
    const float a = 0.5f * v;
    return fmaf(a, t, a);
}

// ---------------- fused prep: weights + fp16 images + zero scratch ----------
#define PREP_NB   (8 * 128 * LDH)               // 139264
__global__ void prep_all(const float* __restrict__ We1, const float* __restrict__ We2,
                         const float* __restrict__ Wx1, const float* __restrict__ Wh1,
                         const float* __restrict__ Wh2,
                         const float* __restrict__ h, const float* __restrict__ ea,
                         int nh, int nea) {
    const int idx = blockIdx.x * 256 + threadIdx.x;
    if (idx < PREP_NB) {
        const int chunk = idx / (128 * LDH);
        const int rem = idx % (128 * LDH);
        const int n = rem / LDH, k = rem % LDH;
        float v = 0.f;
        if (chunk == 0)      { if (k < 128) v = We1[k * 128 + n]; }
        else if (chunk == 1) { if (k < 128) v = We1[(128 + k) * 128 + n]; }
        else if (chunk == 2) { if (k < 16) v = We1[(257 + k) * 128 + n];
                               else if (k == 16) v = We1[256 * 128 + n]; }
        else if (chunk == 3) { if (k < 128) v = We2[k * 128 + n]; }
        else if (chunk == 4) { if (k < 128) v = Wx1[k * 128 + n]; }
        else if (chunk == 5) { if (k < 128) v = Wh1[k * 128 + n]; }
        else if (chunk == 6) { if (k < 128) v = Wh1[(128 + k) * 128 + n]; }
        else                 { if (k < 128) v = Wh2[k * 128 + n]; }
        g_B[idx] = __float2half_rn(v);
    } else if (idx < PREP_NB + nh) {
        const int i = idx - PREP_NB;
        g_h16[i] = __float2half_rn(h[i]);
        g_msg[i] = 0.f;                          // zero msg accumulator
        if (i < MAX_N * 3) g_coord[i] = 0.f;     // zero coord accumulator
    } else if (idx < PREP_NB + nh + nea) {
        g_ea16[idx - PREP_NB - nh] = __float2half_rn(ea[idx - PREP_NB - nh]);
    }
}

// ---------------- mma / ldmatrix / cp.async (R9-proven) ----------------
__device__ __forceinline__ void mma_f16(float* d, const uint32_t* a, const uint32_t* b) {
    asm volatile(
        "mma.sync.aligned.m16n8k16.row.col.f32.f16.f16.f32 "
        "{%0,%1,%2,%3}, {%4,%5,%6,%7}, {%8,%9}, {%0,%1,%2,%3};"
        : "+f"(d[0]), "+f"(d[1]), "+f"(d[2]), "+f"(d[3])
        : "r"(a[0]), "r"(a[1]), "r"(a[2]), "r"(a[3]), "r"(b[0]), "r"(b[1]));
}
__device__ __forceinline__ void ldsm_x4(uint32_t& r0, uint32_t& r1, uint32_t& r2,
                                        uint32_t& r3, uint32_t saddr) {
    asm volatile("ldmatrix.sync.aligned.m8n8.x4.shared.b16 {%0,%1,%2,%3}, [%4];"
                 : "=r"(r0), "=r"(r1), "=r"(r2), "=r"(r3) : "r"(saddr));
}
__device__ __forceinline__ void cp16(uint32_t saddr, const void* gptr) {
    asm volatile("cp.async.cg.shared.global [%0], [%1], 16;"
                 :: "r"(saddr), "l"(gptr));
}
#define CP_COMMIT() asm volatile("cp.async.commit_group;" ::: "memory")
#define CP_WAIT1()  asm volatile("cp.async.wait_group 1;" ::: "memory")
#define CP_WAIT0()  asm volatile("cp.async.wait_group 0;" ::: "memory")

#define BCOPY_ASYNC(DSTU32, CHUNK)                                              \
    do {                                                                        \
        const char* gsrc = (const char*)(g_B + (CHUNK) * 128 * LDH);            \
        for (int i = tid * 16; i < 128 * LDH * 2; i += THREADS * 16)            \
            cp16((DSTU32) + i, gsrc + i);                                       \
        CP_COMMIT();                                                            \
    } while (0)

// gather 128 rows (256B) from g_h16; 2 threads/row, one group
#define AGATHER_ASYNC(IDXEXPR)                                                  \
    do {                                                                        \
        const int r_ = tid >> 1;                                                \
        const int ho_ = (tid & 1) * 64;                                         \
        const long eg_ = base + r_;                                             \
        const int nd_ = IDXEXPR;                                                \
        const __half* src_ = g_h16 + (long)nd_ * H_DIM + ho_;                   \
        const uint32_t dst_ = sa_u + (uint32_t)(r_ * LDH + ho_) * 2;            \
        _Pragma("unroll")                                                       \
        for (int i_ = 0; i_ < 8; i_++) cp16(dst_ + i_ * 16, src_ + i_ * 8);     \
        CP_COMMIT();                                                            \
    } while (0)

// smem layout (byte offsets)
#define OFF_A    0                 // half[128*LDH] = 34816
#define OFF_B0   34816
#define OFF_B1   69632
#define OFF_BE1  104448            // float[128]
#define OFF_BE2  104960
#define OFF_BX1  105472
#define OFF_WX2  105984
#define OFF_DIFF 106496            // float[384]
#define OFF_DST  108032            // int[128]
#define OFF_PART 108544            // float[256]
#define SMEM_BYTES 109568

#define MMA_SWEEP(SA_U32, SB_U32, NST)                                          \
    for (int s = 0; s < (NST); s++) {                                           \
        const int k0 = s * 16;                                                  \
        uint32_t a[2][4], b[8][2];                                              \
        _Pragma("unroll")                                                       \
        for (int mt = 0; mt < 2; mt++)                                          \
            ldsm_x4(a[mt][0], a[mt][1], a[mt][2], a[mt][3],                     \
                    (SA_U32) + (uint32_t)(((rb + mt * 16 + rA) * LDH + k0 + kA) * 2)); \
        _Pragma("unroll")                                                       \
        for (int ntp = 0; ntp < 8; ntp += 2)                                    \
            ldsm_x4(b[ntp][0], b[ntp][1], b[ntp + 1][0], b[ntp + 1][1],         \
                    (SB_U32) + (uint32_t)(((nB + ntp * 8) * LDH + k0 + kB) * 2)); \
        _Pragma("unroll")                                                       \
        for (int mt = 0; mt < 2; mt++)                                          \
            _Pragma("unroll")                                                   \
            for (int nt = 0; nt < 8; nt++) mma_f16(acc[mt][nt], a[mt], b[nt]);  \
    }

// ---------------------------------------------------------------------------
// Edge kernel
// ---------------------------------------------------------------------------
__global__ void __launch_bounds__(THREADS, 2)
egnn_edge_mma(const float* __restrict__ x,
              const int* __restrict__ ei,
              const float* __restrict__ be1, const float* __restrict__ be2,
              const float* __restrict__ bx1, const float* __restrict__ Wx2,
              const float* __restrict__ bx2, int E_) {
    extern __shared__ char smraw[];
    __half* sA   = (__half*)(smraw + OFF_A);
    float* sBE1  = (float*)(smraw + OFF_BE1);
    float* sBE2  = (float*)(smraw + OFF_BE2);
    float* sBX1  = (float*)(smraw + OFF_BX1);
    float* sWX2  = (float*)(smraw + OFF_WX2);
    float* sDIFF = (float*)(smraw + OFF_DIFF);
    int*   sDST  = (int*)(smraw + OFF_DST);
    float* sPART = (float*)(smraw + OFF_PART);

    const int tid = threadIdx.x, warp = tid >> 5, lane = tid & 31;
    const int g = lane >> 2, c = lane & 3;
    const int warpM = warp >> 1, warpN = warp & 1;
    const int rb = warpM * 32, cb = warpN * 64;
    const long base = (long)blockIdx.x * ETILE;

    const int rA = (lane & 7) + ((lane >> 3) & 1) * 8;
    const int kA = ((lane >> 4) & 1) * 8;
    const int nB = cb + ((lane >> 4) & 1) * 8 + (lane & 7);
    const int kB = ((lane >> 3) & 1) * 8;
    const uint32_t smem_u = (uint32_t)__cvta_generic_to_shared(smraw);
    const uint32_t sa_u = smem_u + OFF_A;
    const uint32_t sb0_u = smem_u + OFF_B0;
    const uint32_t sb1_u = smem_u + OFF_B1;

    float acc[2][8][4];
#pragma unroll
    for (int mt = 0; mt < 2; mt++)
#pragma unroll
        for (int nt = 0; nt < 8; nt++)
#pragma unroll
            for (int j = 0; j < 4; j++) acc[mt][nt][j] = 0.f;

    // groups: [A-src], [B0], [B1]
    AGATHER_ASYNC((eg_ < E_) ? ei[eg_] : 0);
    BCOPY_ASYNC(sb0_u, 0);
    BCOPY_ASYNC(sb1_u, 1);

    // all biases + Wx2 once (overlap with async groups)
    if (tid < 128) {
        sBE1[tid] = be1[tid];
        sBE2[tid] = be2[tid];
    } else {
        sBX1[tid - 128] = bx1[tid - 128];
        sWX2[tid - 128] = Wx2[tid - 128];
    }

    // meta: one edge per thread (tid < 128)
    if (tid < 128) {
        const int r = tid;
        const long eg = base + r;
        int sn = 0, dn = 0;
        if (eg < E_) { sn = ei[eg]; dn = ei[(long)E_ + eg]; }
        sDST[r] = dn;
        const float dx = x[sn * 3 + 0] - x[dn * 3 + 0];
        const float dy = x[sn * 3 + 1] - x[dn * 3 + 1];
        const float dz = x[sn * 3 + 2] - x[dn * 3 + 2];
        sDIFF[r * 3 + 0] = dx; sDIFF[r * 3 + 1] = dy; sDIFF[r * 3 + 2] = dz;
        sPART[r] = (dx * dx + dy * dy + dz * dz) * 0.01f;
    }
    CP_WAIT1();                            // A-src + B0 ready
    __syncthreads();
    MMA_SWEEP(sa_u, sb0_u, 8)              // GEMM1 chunk0
    __syncthreads();

    // [A-dst], [B2]
    AGATHER_ASYNC((eg_ < E_) ? ei[(long)E_ + eg_] : 0);
    BCOPY_ASYNC(sb0_u, 2);
    CP_WAIT1();                            // B1 + A-dst ready
    __syncthreads();
    MMA_SWEEP(sa_u, sb1_u, 8)              // GEMM1 chunk1
    __syncthreads();

    // tail A: ea cols 0..15 via cp16, dist col 16; cols 17..31 x zero-B = 0
    {
        const int r = tid >> 1, seg = tid & 1;
        const long eg = base + r;
        const long ee = (eg < E_) ? eg : 0;
        cp16(sa_u + (uint32_t)(r * LDH) * 2 + seg * 16,
             g_ea16 + ee * ED_DIM + seg * 8);
        CP_COMMIT();                       // [ea]
    }
    if (tid < 128) sA[tid * LDH + 16] = __float2half_rn(sPART[tid]);
    BCOPY_ASYNC(sb1_u, 3);                 // [We2]
    CP_WAIT1();                            // B2 + ea ready
    __syncthreads();
    MMA_SWEEP(sa_u, sb0_u, 2)              // GEMM1 tail
    __syncthreads();

    // epi1: m1 = silu(acc + be1) -> sA
#pragma unroll
    for (int mt = 0; mt < 2; mt++) {
        const int r0 = rb + mt * 16 + g;
#pragma unroll
        for (int nt = 0; nt < 8; nt++) {
            const int col = cb + nt * 8 + 2 * c;
            float* a4 = acc[mt][nt];
            *(__half2*)(sA + r0 * LDH + col) = __floats2half2_rn(
                silu_t(a4[0] + sBE1[col]), silu_t(a4[1] + sBE1[col + 1]));
            *(__half2*)(sA + (r0 + 8) * LDH + col) = __floats2half2_rn(
                silu_t(a4[2] + sBE1[col]), silu_t(a4[3] + sBE1[col + 1]));
            a4[0] = a4[1] = a4[2] = a4[3] = 0.f;
        }
    }
    BCOPY_ASYNC(sb0_u, 4);                 // [Wx1]
    CP_WAIT1();                            // We2 ready
    __syncthreads();
    MMA_SWEEP(sa_u, sb1_u, 8)              // GEMM2
    __syncthreads();   // REQUIRED: partner warp (same rows, other col-half)
                       // reads all 128 cols of shared A rows during its sweep;
                       // epi2 below overwrites this warp's col-half.

    // epi2: m_ij = silu(acc+be2); float4 RED to g_msg (R9-proven); -> sA
#pragma unroll
    for (int mt = 0; mt < 2; mt++) {
        const int r0 = rb + mt * 16 + g;
        const int r1 = r0 + 8;
        const int dn0 = sDST[r0], dn1 = sDST[r1];
        const bool v0 = (base + r0) < E_, v1 = (base + r1) < E_;
#pragma unroll
        for (int nt = 0; nt < 8; nt++) {
            const int col = cb + nt * 8 + 2 * c;
            float* a4 = acc[mt][nt];
            const float m00 = silu_t(a4[0] + sBE2[col]);
            const float m01 = silu_t(a4[1] + sBE2[col + 1]);
            const float m10 = silu_t(a4[2] + sBE2[col]);
            const float m11 = silu_t(a4[3] + sBE2[col + 1]);
            const float s00 = __shfl_xor_sync(0xffffffffu, m00, 1);
            const float s01 = __shfl_xor_sync(0xffffffffu, m01, 1);
            const float s10 = __shfl_xor_sync(0xffffffffu, m10, 1);
            const float s11 = __shfl_xor_sync(0xffffffffu, m11, 1);
            if ((c & 1) == 0) {
                if (v0) {
                    float4 f4 = make_float4(m00, m01, s00, s01);
                    atomicAdd((float4*)(g_msg + (long)dn0 * H_DIM + col), f4);
                }
            } else {
                if (v1) {
                    float4 f4 = make_float4(s10, s11, m10, m11);
                    atomicAdd((float4*)(g_msg + (long)dn1 * H_DIM + col - 2), f4);
                }
            }
            *(__half2*)(sA + r0 * LDH + col) = __floats2half2_rn(m00, m01);
            *(__half2*)(sA + r1 * LDH + col) = __floats2half2_rn(m10, m11);
            a4[0] = a4[1] = a4[2] = a4[3] = 0.f;
        }
    }
    CP_WAIT0();                            // Wx1 ready
    __syncthreads();
    MMA_SWEEP(sa_u, sb0_u, 8)              // GEMM3
    // no barrier needed: epi3 writes only sPART (disjoint per warp), not sA

    // epi3: silu, dot Wx2, lane-reduce, tanh, coord scatter
    {
        float p[4] = {0.f, 0.f, 0.f, 0.f};
#pragma unroll
        for (int mt = 0; mt < 2; mt++) {
#pragma unroll
            for (int nt = 0; nt < 8; nt++) {
                const int col = cb + nt * 8 + 2 * c;
                const float w0 = sWX2[col], w1 = sWX2[col + 1];
                float* a4 = acc[mt][nt];
                p[mt * 2 + 0] += silu_t(a4[0] + sBX1[col]) * w0 + silu_t(a4[1] + sBX1[col + 1]) * w1;
                p[mt * 2 + 1] += silu_t(a4[2] + sBX1[col]) * w0 + silu_t(a4[3] + sBX1[col + 1]) * w1;
            }
        }
#pragma unroll
        for (int off = 1; off <= 2; off <<= 1) {
#pragma unroll
            for (int j = 0; j < 4; j++) p[j] += __shfl_xor_sync(0xffffffffu, p[j], off);
        }
        if (c == 0) {
#pragma unroll
            for (int mt = 0; mt < 2; mt++) {
                sPART[(rb + mt * 16 + g) + warpN * 128] = p[mt * 2 + 0];
                sPART[(rb + mt * 16 + g + 8) + warpN * 128] = p[mt * 2 + 1];
            }
        }
    }
    __syncthreads();
    if (tid < 128) {
        const long eg = base + tid;
        if (eg < E_) {
            const float w = tanhf(sPART[tid] + sPART[tid + 128] + __ldg(bx2));
            const int dn = sDST[tid];
            atomicAdd(&g_coord[dn * 3 + 0], sDIFF[tid * 3 + 0] * w);
            atomicAdd(&g_coord[dn * 3 + 1], sDIFF[tid * 3 + 1] * w);
            atomicAdd(&g_coord[dn * 3 + 2], sDIFF[tid * 3 + 2] * w);
        }
    }
}

// ---------------------------------------------------------------------------
// Node kernel: exact R9 design (256 threads, 2 blocks/SM)
// ---------------------------------------------------------------------------
#define NOFF_A    0
#define NOFF_B0   34816
#define NOFF_B1   69632
#define NOFF_BH1  104448
#define NOFF_B2F  104960
#define NSMEM_BYTES 105472

__global__ void __launch_bounds__(THREADS, 2)
egnn_node_mma(const float* __restrict__ h, const float* __restrict__ x,
              const int* __restrict__ fixedm,
              const float* __restrict__ bh1, const float* __restrict__ bh2,
              float* __restrict__ out_h, float* __restrict__ out_x, int N_) {
    extern __shared__ char smraw[];
    __half* sA   = (__half*)(smraw + NOFF_A);
    float* sBH1  = (float*)(smraw + NOFF_BH1);
    float* sB2   = (float*)(smraw + NOFF_B2F);

    const int tid = threadIdx.x, warp = tid >> 5, lane = tid & 31;
    const int g = lane >> 2, c = lane & 3;
    const int warpM = warp >> 1, warpN = warp & 1;
    const int rb = warpM * 32, cb = warpN * 64;
    const long base = (long)blockIdx.x * ETILE;

    const int rA = (lane & 7) + ((lane >> 3) & 1) * 8;
    const int kA = ((lane >> 4) & 1) * 8;
    const int nB = cb + ((lane >> 4) & 1) * 8 + (lane & 7);
    const int kB = ((lane >> 3) & 1) * 8;
    const uint32_t smem_u = (uint32_t)__cvta_generic_to_shared(smraw);
    const uint32_t sa_u = smem_u + NOFF_A;
    const uint32_t sb0_u = smem_u + NOFF_B0;
    const uint32_t sb1_u = smem_u + NOFF_B1;

    float acc[2][8][4];
#pragma unroll
    for (int mt = 0; mt < 2; mt++)
#pragma unroll
        for (int nt = 0; nt < 8; nt++)
#pragma unroll
            for (int j = 0; j < 4; j++) acc[mt][nt][j] = 0.f;

    // [A-h], [B5], [B6]
    {
        const int r_ = tid >> 1;
        const int ho_ = (tid & 1) * 64;
        long node = base + r_;
        if (node >= N_) node = N_ - 1;
        const __half* src_ = g_h16 + node * H_DIM + ho_;
        const uint32_t dst_ = sa_u + (uint32_t)(r_ * LDH + ho_) * 2;
#pragma unroll
        for (int i_ = 0; i_ < 8; i_++) cp16(dst_ + i_ * 16, src_ + i_ * 8);
        CP_COMMIT();
    }
    for (int i = tid * 16; i < 128 * LDH * 2; i += THREADS * 16)
        cp16(sb0_u + i, (const char*)(g_B + 5 * 128 * LDH) + i);
    CP_COMMIT();
    for (int i = tid * 16; i < 128 * LDH * 2; i += THREADS * 16)
        cp16(sb1_u + i, (const char*)(g_B + 6 * 128 * LDH) + i);
    CP_COMMIT();
    if (tid < 128) sBH1[tid] = bh1[tid];
    else sB2[tid - 128] = bh2[tid - 128];
    CP_WAIT1();
    __syncthreads();
    MMA_SWEEP(sa_u, sb0_u, 8)               // h @ Wh1[0:128]
    __syncthreads();

    // A = msg rows (fp32 -> fp16)
#pragma unroll
    for (int i = 0; i < 16; i++) {
        const int r = warp * 16 + i;
        const long node = base + r;
        float4 v = make_float4(0.f, 0.f, 0.f, 0.f);
        if (node < N_) v = *(const float4*)(g_msg + node * H_DIM + lane * 4);
        __half2* dstp = (__half2*)(sA + r * LDH + lane * 4);
        dstp[0] = __floats2half2_rn(v.x, v.y);
        dstp[1] = __floats2half2_rn(v.z, v.w);
    }
    for (int i = tid * 16; i < 128 * LDH * 2; i += THREADS * 16)
        cp16(sb0_u + i, (const char*)(g_B + 7 * 128 * LDH) + i);
    CP_COMMIT();
    CP_WAIT1();
    __syncthreads();
    MMA_SWEEP(sa_u, sb1_u, 8)               // msg @ Wh1[128:256]
    __syncthreads();

    // epi1: u = silu(acc + bh1) -> sA
#pragma unroll
    for (int mt = 0; mt < 2; mt++) {
        const int r0 = rb + mt * 16 + g;
#pragma unroll
        for (int nt = 0; nt < 8; nt++) {
            const int col = cb + nt * 8 + 2 * c;
            float* a4 = acc[mt][nt];
            *(__half2*)(sA + r0 * LDH + col) = __floats2half2_rn(
                silu_t(a4[0] + sBH1[col]), silu_t(a4[1] + sBH1[col + 1]));
            *(__half2*)(sA + (r0 + 8) * LDH + col) = __floats2half2_rn(
                silu_t(a4[2] + sBH1[col]), silu_t(a4[3] + sBH1[col + 1]));
            a4[0] = a4[1] = a4[2] = a4[3] = 0.f;
        }
    }
    CP_WAIT0();
    __syncthreads();
    MMA_SWEEP(sa_u, sb0_u, 8)               // u @ Wh2
    // epi2 writes only gmem (not sA) -> no barrier needed

    // epi2: out_h = h + acc + bh2
#pragma unroll
    for (int mt = 0; mt < 2; mt++) {
        const int r0 = rb + mt * 16 + g;
        const int r1 = r0 + 8;
        const long n0 = base + r0, n1 = base + r1;
#pragma unroll
        for (int nt = 0; nt < 8; nt++) {
            const int col = cb + nt * 8 + 2 * c;
            float* a4 = acc[mt][nt];
            if (n0 < N_) {
                const float2 hh = *(const float2*)(h + n0 * H_DIM + col);
                float2 o;
                o.x = a4[0] + sB2[col] + hh.x;
                o.y = a4[1] + sB2[col + 1] + hh.y;
                *(float2*)(out_h + n0 * H_DIM + col) = o;
            }
            if (n1 < N_) {
                const float2 hh = *(const float2*)(h + n1 * H_DIM + col);
                float2 o;
                o.x = a4[2] + sB2[col] + hh.x;
                o.y = a4[3] + sB2[col + 1] + hh.y;
                *(float2*)(out_h + n1 * H_DIM + col) = o;
            }
        }
    }
    for (int idx = tid; idx < ETILE * 3; idx += THREADS) {
        const int li = idx / 3, cc = idx - li * 3;
        const long node = base + li;
        if (node < N_) {
            const float add = fixedm[node] ? 0.f : g_coord[node * 3 + cc];
            out_x[node * 3 + cc] = x[node * 3 + cc] + add;
        }
    }
}

// ---------------------------------------------------------------------------
extern "C" void kernel_launch(void* const* d_in, const int* in_sizes, int n_in,
                              void* d_out, int out_size) {
    const float* h   = (const float*)d_in[0];
    const float* x   = (const float*)d_in[1];
    const int* ei    = (const int*)d_in[2];
    const float* ea  = (const float*)d_in[3];
    const int* fixedm = (const int*)d_in[4];
    const float* We1 = (const float*)d_in[5];
    const float* be1 = (const float*)d_in[6];
    const float* We2 = (const float*)d_in[7];
    const float* be2 = (const float*)d_in[8];
    const float* Wx1 = (const float*)d_in[9];
    const float* bx1 = (const float*)d_in[10];
    const float* Wx2 = (const float*)d_in[11];
    const float* bx2 = (const float*)d_in[12];
    const float* Wh1 = (const float*)d_in[13];
    const float* bh1 = (const float*)d_in[14];
    const float* Wh2 = (const float*)d_in[15];
    const float* bh2 = (const float*)d_in[16];

    const int N_ = in_sizes[0] / H_DIM;
    const int E_ = in_sizes[3] / ED_DIM;

    float* out_h = (float*)d_out;
    float* out_x = out_h + (long)N_ * H_DIM;

    const int nh = N_ * H_DIM, nea = E_ * ED_DIM;
    const int nprep = PREP_NB + nh + nea;
    prep_all<<<(nprep + 255) / 256, 256>>>(We1, We2, Wx1, Wh1, Wh2, h, ea, nh, nea);

    cudaFuncSetAttribute(egnn_edge_mma, cudaFuncAttributeMaxDynamicSharedMemorySize, SMEM_BYTES);
    const int eBlocks = (E_ + ETILE - 1) / ETILE;
    egnn_edge_mma<<<eBlocks, THREADS, SMEM_BYTES>>>(x, ei, be1, be2, bx1, Wx2, bx2, E_);

    cudaFuncSetAttribute(egnn_node_mma, cudaFuncAttributeMaxDynamicSharedMemorySize, NSMEM_BYTES);
    const int nBlocks = (N_ + ETILE - 1) / ETILE;
    egnn_node_mma<<<nBlocks, THREADS, NSMEM_BYTES>>>(h, x, fixedm, bh1, bh2,
                                                     out_h, out_x, N_);
}

// round 17
// speedup vs baseline: 1.0499x; 1.0499x over previous
#include <cuda_runtime.h>
#include <cuda_fp16.h>
#include <math.h>
#include <stdint.h>

#define H_DIM 128
#define ED_DIM 16
#define ETILE 128
#define THREADS 256
#define MAX_N 20000
#define MAX_E 640000
#define LDH 136            // half pitch; 272B rows -> ldmatrix conflict-free

// ---------------- device scratch ----------------
__device__ __align__(16) float g_msg[MAX_N * H_DIM];
__device__ __align__(16) float g_coord[MAX_N * 3];
__device__ __align__(16) __half g_h16[MAX_N * H_DIM];
__device__ __align__(16) __half g_ea16[MAX_E * ED_DIM];
// 8 chunks [128][LDH]: 0,1=We1 k0..255, 2=We1 tail(ea rows 0..15, dist row 16),
// 3=We2, 4=Wx1, 5,6=Wh1, 7=Wh2
__device__ __align__(16) __half g_B[8 * 128 * LDH];

// silu via tanh.approx.f32 (R8-proven)
__device__ __forceinline__ float silu_t(float v) {
    float t;
    asm("tanh.approx.f32 %0, %1;" : "=f"(t) : "f"(v * 0.5f));
    const float a = 0.5f * v;
    return fmaf(a, t, a);
}

// ---------------- fused prep: weights (scalar) + vectorized conversions ------
#define PREP_NB   (8 * 128 * LDH)               // 139264
__global__ void prep_all(const float* __restrict__ We1, const float* __restrict__ We2,
                         const float* __restrict__ Wx1, const float* __restrict__ Wh1,
                         const float* __restrict__ Wh2,
                         const float* __restrict__ h, const float* __restrict__ ea,
                         int nh, int nea) {
    const int idx = blockIdx.x * 256 + threadIdx.x;
    if (idx < PREP_NB) {
        const int chunk = idx / (128 * LDH);
        const int rem = idx % (128 * LDH);
        const int n = rem / LDH, k = rem % LDH;
        float v = 0.f;
        if (chunk == 0)      { if (k < 128) v = We1[k * 128 + n]; }
        else if (chunk == 1) { if (k < 128) v = We1[(128 + k) * 128 + n]; }
        else if (chunk == 2) { if (k < 16) v = We1[(257 + k) * 128 + n];
                               else if (k == 16) v = We1[256 * 128 + n]; }
        else if (chunk == 3) { if (k < 128) v = We2[k * 128 + n]; }
        else if (chunk == 4) { if (k < 128) v = Wx1[k * 128 + n]; }
        else if (chunk == 5) { if (k < 128) v = Wh1[k * 128 + n]; }
        else if (chunk == 6) { if (k < 128) v = Wh1[(128 + k) * 128 + n]; }
        else                 { if (k < 128) v = Wh2[k * 128 + n]; }
        g_B[idx] = __float2half_rn(v);
    } else {
        const int i = (idx - PREP_NB) * 4;      // 4 elements per thread
        if (i < nh) {
            const float4 hv = *(const float4*)(h + i);
            __half2 lo = __floats2half2_rn(hv.x, hv.y);
            __half2 hi = __floats2half2_rn(hv.z, hv.w);
            uint2 packed;
            packed.x = *(uint32_t*)&lo;
            packed.y = *(uint32_t*)&hi;
            *(uint2*)(g_h16 + i) = packed;
            *(float4*)(g_msg + i) = make_float4(0.f, 0.f, 0.f, 0.f);
            if (i < MAX_N * 3)
                *(float4*)(g_coord + i) = make_float4(0.f, 0.f, 0.f, 0.f);
        } else if (i - nh < nea) {
            const int j = i - nh;
            const float4 ev = *(const float4*)(ea + j);
            __half2 lo = __floats2half2_rn(ev.x, ev.y);
            __half2 hi = __floats2half2_rn(ev.z, ev.w);
            uint2 packed;
            packed.x = *(uint32_t*)&lo;
            packed.y = *(uint32_t*)&hi;
            *(uint2*)(g_ea16 + j) = packed;
        }
    }
}

// ---------------- mma / ldmatrix / cp.async (R9-proven) ----------------
__device__ __forceinline__ void mma_f16(float* d, const uint32_t* a, const uint32_t* b) {
    asm volatile(
        "mma.sync.aligned.m16n8k16.row.col.f32.f16.f16.f32 "
        "{%0,%1,%2,%3}, {%4,%5,%6,%7}, {%8,%9}, {%0,%1,%2,%3};"
        : "+f"(d[0]), "+f"(d[1]), "+f"(d[2]), "+f"(d[3])
        : "r"(a[0]), "r"(a[1]), "r"(a[2]), "r"(a[3]), "r"(b[0]), "r"(b[1]));
}
__device__ __forceinline__ void ldsm_x4(uint32_t& r0, uint32_t& r1, uint32_t& r2,
                                        uint32_t& r3, uint32_t saddr) {
    asm volatile("ldmatrix.sync.aligned.m8n8.x4.shared.b16 {%0,%1,%2,%3}, [%4];"
                 : "=r"(r0), "=r"(r1), "=r"(r2), "=r"(r3) : "r"(saddr));
}
__device__ __forceinline__ void cp16(uint32_t saddr, const void* gptr) {
    asm volatile("cp.async.cg.shared.global [%0], [%1], 16;"
                 :: "r"(saddr), "l"(gptr));
}
#define CP_COMMIT() asm volatile("cp.async.commit_group;" ::: "memory")
#define CP_WAIT1()  asm volatile("cp.async.wait_group 1;" ::: "memory")
#define CP_WAIT0()  asm volatile("cp.async.wait_group 0;" ::: "memory")

#define BCOPY_ASYNC(DSTU32, CHUNK)                                              \
    do {                                                                        \
        const char* gsrc = (const char*)(g_B + (CHUNK) * 128 * LDH);            \
        for (int i = tid * 16; i < 128 * LDH * 2; i += THREADS * 16)            \
            cp16((DSTU32) + i, gsrc + i);                                       \
        CP_COMMIT();                                                            \
    } while (0)

// gather 128 rows (256B) from g_h16; 2 threads/row, one group
#define AGATHER_ASYNC(IDXEXPR)                                                  \
    do {                                                                        \
        const int r_ = tid >> 1;                                                \
        const int ho_ = (tid & 1) * 64;                                         \
        const long eg_ = base + r_;                                             \
        const int nd_ = IDXEXPR;                                                \
        const __half* src_ = g_h16 + (long)nd_ * H_DIM + ho_;                   \
        const uint32_t dst_ = sa_u + (uint32_t)(r_ * LDH + ho_) * 2;            \
        _Pragma("unroll")                                                       \
        for (int i_ = 0; i_ < 8; i_++) cp16(dst_ + i_ * 16, src_ + i_ * 8);     \
        CP_COMMIT();                                                            \
    } while (0)

// smem layout (byte offsets)
#define OFF_A    0                 // half[128*LDH] = 34816
#define OFF_B0   34816
#define OFF_B1   69632
#define OFF_BE1  104448            // float[128]
#define OFF_BE2  104960
#define OFF_BX1  105472
#define OFF_WX2  105984
#define OFF_DIFF 106496            // float[384]
#define OFF_DST  108032            // int[128]
#define OFF_PART 108544            // float[256]
#define SMEM_BYTES 109568

#define MMA_SWEEP(SA_U32, SB_U32, NST)                                          \
    for (int s = 0; s < (NST); s++) {                                           \
        const int k0 = s * 16;                                                  \
        uint32_t a[2][4], b[8][2];                                              \
        _Pragma("unroll")                                                       \
        for (int mt = 0; mt < 2; mt++)                                          \
            ldsm_x4(a[mt][0], a[mt][1], a[mt][2], a[mt][3],                     \
                    (SA_U32) + (uint32_t)(((rb + mt * 16 + rA) * LDH + k0 + kA) * 2)); \
        _Pragma("unroll")                                                       \
        for (int ntp = 0; ntp < 8; ntp += 2)                                    \
            ldsm_x4(b[ntp][0], b[ntp][1], b[ntp + 1][0], b[ntp + 1][1],         \
                    (SB_U32) + (uint32_t)(((nB + ntp * 8) * LDH + k0 + kB) * 2)); \
        _Pragma("unroll")                                                       \
        for (int mt = 0; mt < 2; mt++)                                          \
            _Pragma("unroll")                                                   \
            for (int nt = 0; nt < 8; nt++) mma_f16(acc[mt][nt], a[mt], b[nt]);  \
    }

// ---------------------------------------------------------------------------
// Edge kernel (R16-proven, race-free)
// ---------------------------------------------------------------------------
__global__ void __launch_bounds__(THREADS, 2)
egnn_edge_mma(const float* __restrict__ x,
              const int* __restrict__ ei,
              const float* __restrict__ be1, const float* __restrict__ be2,
              const float* __restrict__ bx1, const float* __restrict__ Wx2,
              const float* __restrict__ bx2, int E_) {
    extern __shared__ char smraw[];
    __half* sA   = (__half*)(smraw + OFF_A);
    float* sBE1  = (float*)(smraw + OFF_BE1);
    float* sBE2  = (float*)(smraw + OFF_BE2);
    float* sBX1  = (float*)(smraw + OFF_BX1);
    float* sWX2  = (float*)(smraw + OFF_WX2);
    float* sDIFF = (float*)(smraw + OFF_DIFF);
    int*   sDST  = (int*)(smraw + OFF_DST);
    float* sPART = (float*)(smraw + OFF_PART);

    const int tid = threadIdx.x, warp = tid >> 5, lane = tid & 31;
    const int g = lane >> 2, c = lane & 3;
    const int warpM = warp >> 1, warpN = warp & 1;
    const int rb = warpM * 32, cb = warpN * 64;
    const long base = (long)blockIdx.x * ETILE;

    const int rA = (lane & 7) + ((lane >> 3) & 1) * 8;
    const int kA = ((lane >> 4) & 1) * 8;
    const int nB = cb + ((lane >> 4) & 1) * 8 + (lane & 7);
    const int kB = ((lane >> 3) & 1) * 8;
    const uint32_t smem_u = (uint32_t)__cvta_generic_to_shared(smraw);
    const uint32_t sa_u = smem_u + OFF_A;
    const uint32_t sb0_u = smem_u + OFF_B0;
    const uint32_t sb1_u = smem_u + OFF_B1;

    float acc[2][8][4];
#pragma unroll
    for (int mt = 0; mt < 2; mt++)
#pragma unroll
        for (int nt = 0; nt < 8; nt++)
#pragma unroll
            for (int j = 0; j < 4; j++) acc[mt][nt][j] = 0.f;

    // groups: [A-src], [B0], [B1]
    AGATHER_ASYNC((eg_ < E_) ? ei[eg_] : 0);
    BCOPY_ASYNC(sb0_u, 0);
    BCOPY_ASYNC(sb1_u, 1);

    // all biases + Wx2 once (overlap with async groups)
    if (tid < 128) {
        sBE1[tid] = be1[tid];
        sBE2[tid] = be2[tid];
    } else {
        sBX1[tid - 128] = bx1[tid - 128];
        sWX2[tid - 128] = Wx2[tid - 128];
    }

    // meta: one edge per thread (tid < 128)
    if (tid < 128) {
        const int r = tid;
        const long eg = base + r;
        int sn = 0, dn = 0;
        if (eg < E_) { sn = ei[eg]; dn = ei[(long)E_ + eg]; }
        sDST[r] = dn;
        const float dx = x[sn * 3 + 0] - x[dn * 3 + 0];
        const float dy = x[sn * 3 + 1] - x[dn * 3 + 1];
        const float dz = x[sn * 3 + 2] - x[dn * 3 + 2];
        sDIFF[r * 3 + 0] = dx; sDIFF[r * 3 + 1] = dy; sDIFF[r * 3 + 2] = dz;
        sPART[r] = (dx * dx + dy * dy + dz * dz) * 0.01f;
    }
    CP_WAIT1();                            // A-src + B0 ready
    __syncthreads();
    MMA_SWEEP(sa_u, sb0_u, 8)              // GEMM1 chunk0
    __syncthreads();

    // [A-dst], [B2]
    AGATHER_ASYNC((eg_ < E_) ? ei[(long)E_ + eg_] : 0);
    BCOPY_ASYNC(sb0_u, 2);
    CP_WAIT1();                            // B1 + A-dst ready
    __syncthreads();
    MMA_SWEEP(sa_u, sb1_u, 8)              // GEMM1 chunk1
    __syncthreads();

    // tail A: ea cols 0..15 via cp16, dist col 16; cols 17..31 x zero-B = 0
    {
        const int r = tid >> 1, seg = tid & 1;
        const long eg = base + r;
        const long ee = (eg < E_) ? eg : 0;
        cp16(sa_u + (uint32_t)(r * LDH) * 2 + seg * 16,
             g_ea16 + ee * ED_DIM + seg * 8);
        CP_COMMIT();                       // [ea]
    }
    if (tid < 128) sA[tid * LDH + 16] = __float2half_rn(sPART[tid]);
    BCOPY_ASYNC(sb1_u, 3);                 // [We2]
    CP_WAIT1();                            // B2 + ea ready
    __syncthreads();
    MMA_SWEEP(sa_u, sb0_u, 2)              // GEMM1 tail
    __syncthreads();

    // epi1: m1 = silu(acc + be1) -> sA
#pragma unroll
    for (int mt = 0; mt < 2; mt++) {
        const int r0 = rb + mt * 16 + g;
#pragma unroll
        for (int nt = 0; nt < 8; nt++) {
            const int col = cb + nt * 8 + 2 * c;
            float* a4 = acc[mt][nt];
            *(__half2*)(sA + r0 * LDH + col) = __floats2half2_rn(
                silu_t(a4[0] + sBE1[col]), silu_t(a4[1] + sBE1[col + 1]));
            *(__half2*)(sA + (r0 + 8) * LDH + col) = __floats2half2_rn(
                silu_t(a4[2] + sBE1[col]), silu_t(a4[3] + sBE1[col + 1]));
            a4[0] = a4[1] = a4[2] = a4[3] = 0.f;
        }
    }
    BCOPY_ASYNC(sb0_u, 4);                 // [Wx1]
    CP_WAIT1();                            // We2 ready
    __syncthreads();
    MMA_SWEEP(sa_u, sb1_u, 8)              // GEMM2
    __syncthreads();   // REQUIRED: partner warp reads all cols of shared rows

    // epi2: m_ij = silu(acc+be2); float4 RED to g_msg; -> sA
#pragma unroll
    for (int mt = 0; mt < 2; mt++) {
        const int r0 = rb + mt * 16 + g;
        const int r1 = r0 + 8;
        const int dn0 = sDST[r0], dn1 = sDST[r1];
        const bool v0 = (base + r0) < E_, v1 = (base + r1) < E_;
#pragma unroll
        for (int nt = 0; nt < 8; nt++) {
            const int col = cb + nt * 8 + 2 * c;
            float* a4 = acc[mt][nt];
            const float m00 = silu_t(a4[0] + sBE2[col]);
            const float m01 = silu_t(a4[1] + sBE2[col + 1]);
            const float m10 = silu_t(a4[2] + sBE2[col]);
            const float m11 = silu_t(a4[3] + sBE2[col + 1]);
            const float s00 = __shfl_xor_sync(0xffffffffu, m00, 1);
            const float s01 = __shfl_xor_sync(0xffffffffu, m01, 1);
            const float s10 = __shfl_xor_sync(0xffffffffu, m10, 1);
            const float s11 = __shfl_xor_sync(0xffffffffu, m11, 1);
            if ((c & 1) == 0) {
                if (v0) {
                    float4 f4 = make_float4(m00, m01, s00, s01);
                    atomicAdd((float4*)(g_msg + (long)dn0 * H_DIM + col), f4);
                }
            } else {
                if (v1) {
                    float4 f4 = make_float4(s10, s11, m10, m11);
                    atomicAdd((float4*)(g_msg + (long)dn1 * H_DIM + col - 2), f4);
                }
            }
            *(__half2*)(sA + r0 * LDH + col) = __floats2half2_rn(m00, m01);
            *(__half2*)(sA + r1 * LDH + col) = __floats2half2_rn(m10, m11);
            a4[0] = a4[1] = a4[2] = a4[3] = 0.f;
        }
    }
    CP_WAIT0();                            // Wx1 ready
    __syncthreads();
    MMA_SWEEP(sa_u, sb0_u, 8)              // GEMM3
    // no barrier needed: epi3 writes only sPART, not sA

    // epi3: silu, dot Wx2, lane-reduce, tanh, coord scatter
    {
        float p[4] = {0.f, 0.f, 0.f, 0.f};
#pragma unroll
        for (int mt = 0; mt < 2; mt++) {
#pragma unroll
            for (int nt = 0; nt < 8; nt++) {
                const int col = cb + nt * 8 + 2 * c;
                const float w0 = sWX2[col], w1 = sWX2[col + 1];
                float* a4 = acc[mt][nt];
                p[mt * 2 + 0] += silu_t(a4[0] + sBX1[col]) * w0 + silu_t(a4[1] + sBX1[col + 1]) * w1;
                p[mt * 2 + 1] += silu_t(a4[2] + sBX1[col]) * w0 + silu_t(a4[3] + sBX1[col + 1]) * w1;
            }
        }
#pragma unroll
        for (int off = 1; off <= 2; off <<= 1) {
#pragma unroll
            for (int j = 0; j < 4; j++) p[j] += __shfl_xor_sync(0xffffffffu, p[j], off);
        }
        if (c == 0) {
#pragma unroll
            for (int mt = 0; mt < 2; mt++) {
                sPART[(rb + mt * 16 + g) + warpN * 128] = p[mt * 2 + 0];
                sPART[(rb + mt * 16 + g + 8) + warpN * 128] = p[mt * 2 + 1];
            }
        }
    }
    __syncthreads();
    if (tid < 128) {
        const long eg = base + tid;
        if (eg < E_) {
            const float w = tanhf(sPART[tid] + sPART[tid + 128] + __ldg(bx2));
            const int dn = sDST[tid];
            atomicAdd(&g_coord[dn * 3 + 0], sDIFF[tid * 3 + 0] * w);
            atomicAdd(&g_coord[dn * 3 + 1], sDIFF[tid * 3 + 1] * w);
            atomicAdd(&g_coord[dn * 3 + 2], sDIFF[tid * 3 + 2] * w);
        }
    }
}

// ---------------------------------------------------------------------------
// Node kernel: exact R9 design (256 threads, 2 blocks/SM)
// ---------------------------------------------------------------------------
#define NOFF_A    0
#define NOFF_B0   34816
#define NOFF_B1   69632
#define NOFF_BH1  104448
#define NOFF_B2F  104960
#define NSMEM_BYTES 105472

__global__ void __launch_bounds__(THREADS, 2)
egnn_node_mma(const float* __restrict__ h, const float* __restrict__ x,
              const int* __restrict__ fixedm,
              const float* __restrict__ bh1, const float* __restrict__ bh2,
              float* __restrict__ out_h, float* __restrict__ out_x, int N_) {
    extern __shared__ char smraw[];
    __half* sA   = (__half*)(smraw + NOFF_A);
    float* sBH1  = (float*)(smraw + NOFF_BH1);
    float* sB2   = (float*)(smraw + NOFF_B2F);

    const int tid = threadIdx.x, warp = tid >> 5, lane = tid & 31;
    const int g = lane >> 2, c = lane & 3;
    const int warpM = warp >> 1, warpN = warp & 1;
    const int rb = warpM * 32, cb = warpN * 64;
    const long base = (long)blockIdx.x * ETILE;

    const int rA = (lane & 7) + ((lane >> 3) & 1) * 8;
    const int kA = ((lane >> 4) & 1) * 8;
    const int nB = cb + ((lane >> 4) & 1) * 8 + (lane & 7);
    const int kB = ((lane >> 3) & 1) * 8;
    const uint32_t smem_u = (uint32_t)__cvta_generic_to_shared(smraw);
    const uint32_t sa_u = smem_u + NOFF_A;
    const uint32_t sb0_u = smem_u + NOFF_B0;
    const uint32_t sb1_u = smem_u + NOFF_B1;

    float acc[2][8][4];
#pragma unroll
    for (int mt = 0; mt < 2; mt++)
#pragma unroll
        for (int nt = 0; nt < 8; nt++)
#pragma unroll
            for (int j = 0; j < 4; j++) acc[mt][nt][j] = 0.f;

    // [A-h], [B5], [B6]
    {
        const int r_ = tid >> 1;
        const int ho_ = (tid & 1) * 64;
        long node = base + r_;
        if (node >= N_) node = N_ - 1;
        const __half* src_ = g_h16 + node * H_DIM + ho_;
        const uint32_t dst_ = sa_u + (uint32_t)(r_ * LDH + ho_) * 2;
#pragma unroll
        for (int i_ = 0; i_ < 8; i_++) cp16(dst_ + i_ * 16, src_ + i_ * 8);
        CP_COMMIT();
    }
    for (int i = tid * 16; i < 128 * LDH * 2; i += THREADS * 16)
        cp16(sb0_u + i, (const char*)(g_B + 5 * 128 * LDH) + i);
    CP_COMMIT();
    for (int i = tid * 16; i < 128 * LDH * 2; i += THREADS * 16)
        cp16(sb1_u + i, (const char*)(g_B + 6 * 128 * LDH) + i);
    CP_COMMIT();
    if (tid < 128) sBH1[tid] = bh1[tid];
    else sB2[tid - 128] = bh2[tid - 128];
    CP_WAIT1();
    __syncthreads();
    MMA_SWEEP(sa_u, sb0_u, 8)               // h @ Wh1[0:128]
    __syncthreads();

    // A = msg rows (fp32 -> fp16)
#pragma unroll
    for (int i = 0; i < 16; i++) {
        const int r = warp * 16 + i;
        const long node = base + r;
        float4 v = make_float4(0.f, 0.f, 0.f, 0.f);
        if (node < N_) v = *(const float4*)(g_msg + node * H_DIM + lane * 4);
        __half2* dstp = (__half2*)(sA + r * LDH + lane * 4);
        dstp[0] = __floats2half2_rn(v.x, v.y);
        dstp[1] = __floats2half2_rn(v.z, v.w);
    }
    for (int i = tid * 16; i < 128 * LDH * 2; i += THREADS * 16)
        cp16(sb0_u + i, (const char*)(g_B + 7 * 128 * LDH) + i);
    CP_COMMIT();
    CP_WAIT1();
    __syncthreads();
    MMA_SWEEP(sa_u, sb1_u, 8)               // msg @ Wh1[128:256]
    __syncthreads();

    // epi1: u = silu(acc + bh1) -> sA
#pragma unroll
    for (int mt = 0; mt < 2; mt++) {
        const int r0 = rb + mt * 16 + g;
#pragma unroll
        for (int nt = 0; nt < 8; nt++) {
            const int col = cb + nt * 8 + 2 * c;
            float* a4 = acc[mt][nt];
            *(__half2*)(sA + r0 * LDH + col) = __floats2half2_rn(
                silu_t(a4[0] + sBH1[col]), silu_t(a4[1] + sBH1[col + 1]));
            *(__half2*)(sA + (r0 + 8) * LDH + col) = __floats2half2_rn(
                silu_t(a4[2] + sBH1[col]), silu_t(a4[3] + sBH1[col + 1]));
            a4[0] = a4[1] = a4[2] = a4[3] = 0.f;
        }
    }
    CP_WAIT0();
    __syncthreads();
    MMA_SWEEP(sa_u, sb0_u, 8)               // u @ Wh2
    // epi2 writes only gmem (not sA) -> no barrier needed

    // epi2: out_h = h + acc + bh2
#pragma unroll
    for (int mt = 0; mt < 2; mt++) {
        const int r0 = rb + mt * 16 + g;
        const int r1 = r0 + 8;
        const long n0 = base + r0, n1 = base + r1;
#pragma unroll
        for (int nt = 0; nt < 8; nt++) {
            const int col = cb + nt * 8 + 2 * c;
            float* a4 = acc[mt][nt];
            if (n0 < N_) {
                const float2 hh = *(const float2*)(h + n0 * H_DIM + col);
                float2 o;
                o.x = a4[0] + sB2[col] + hh.x;
                o.y = a4[1] + sB2[col + 1] + hh.y;
                *(float2*)(out_h + n0 * H_DIM + col) = o;
            }
            if (n1 < N_) {
                const float2 hh = *(const float2*)(h + n1 * H_DIM + col);
                float2 o;
                o.x = a4[2] + sB2[col] + hh.x;
                o.y = a4[3] + sB2[col + 1] + hh.y;
                *(float2*)(out_h + n1 * H_DIM + col) = o;
            }
        }
    }
    for (int idx = tid; idx < ETILE * 3; idx += THREADS) {
        const int li = idx / 3, cc = idx - li * 3;
        const long node = base + li;
        if (node < N_) {
            const float add = fixedm[node] ? 0.f : g_coord[node * 3 + cc];
            out_x[node * 3 + cc] = x[node * 3 + cc] + add;
        }
    }
}

// ---------------------------------------------------------------------------
extern "C" void kernel_launch(void* const* d_in, const int* in_sizes, int n_in,
                              void* d_out, int out_size) {
    const float* h   = (const float*)d_in[0];
    const float* x   = (const float*)d_in[1];
    const int* ei    = (const int*)d_in[2];
    const float* ea  = (const float*)d_in[3];
    const int* fixedm = (const int*)d_in[4];
    const float* We1 = (const float*)d_in[5];
    const float* be1 = (const float*)d_in[6];
    const float* We2 = (const float*)d_in[7];
    const float* be2 = (const float*)d_in[8];
    const float* Wx1 = (const float*)d_in[9];
    const float* bx1 = (const float*)d_in[10];
    const float* Wx2 = (const float*)d_in[11];
    const float* bx2 = (const float*)d_in[12];
    const float* Wh1 = (const float*)d_in[13];
    const float* bh1 = (const float*)d_in[14];
    const float* Wh2 = (const float*)d_in[15];
    const float* bh2 = (const float*)d_in[16];

    const int N_ = in_sizes[0] / H_DIM;
    const int E_ = in_sizes[3] / ED_DIM;

    float* out_h = (float*)d_out;
    float* out_x = out_h + (long)N_ * H_DIM;

    const int nh = N_ * H_DIM, nea = E_ * ED_DIM;
    const int nprep = PREP_NB + (nh + nea) / 4;
    prep_all<<<(nprep + 255) / 256, 256>>>(We1, We2, Wx1, Wh1, Wh2, h, ea, nh, nea);

    cudaFuncSetAttribute(egnn_edge_mma, cudaFuncAttributeMaxDynamicSharedMemorySize, SMEM_BYTES);
    const int eBlocks = (E_ + ETILE - 1) / ETILE;
    egnn_edge_mma<<<eBlocks, THREADS, SMEM_BYTES>>>(x, ei, be1, be2, bx1, Wx2, bx2, E_);

    cudaFuncSetAttribute(egnn_node_mma, cudaFuncAttributeMaxDynamicSharedMemorySize, NSMEM_BYTES);
    const int nBlocks = (N_ + ETILE - 1) / ETILE;
    egnn_node_mma<<<nBlocks, THREADS, NSMEM_BYTES>>>(h, x, fixedm, bh1, bh2,
                                                     out_h, out_x, N_);
}